// round 4
// baseline (speedup 1.0000x reference)
#include <cuda_runtime.h>
#include <cstdint>

typedef unsigned long long ull;

#define BB 512
#define TT 1024
#define IDIM 15
#define HH 64
#define ODIM 11
#define CHUNK 16
#define NCHUNK (TT/CHUNK)

// scratch (static __device__ — no allocations in kernel_launch)
__device__ __align__(16) float g_xpad[(size_t)BB*TT*16];   // x padded 15 -> 16

// ---- f32x2 helpers ----
__device__ __forceinline__ ull ffma2(ull a, ull b, ull c){
    ull d; asm("fma.rn.f32x2 %0, %1, %2, %3;" : "=l"(d) : "l"(a), "l"(b), "l"(c)); return d;
}
__device__ __forceinline__ ull fadd2(ull a, ull b){
    ull d; asm("add.rn.f32x2 %0, %1, %2;" : "=l"(d) : "l"(a), "l"(b)); return d;
}
__device__ __forceinline__ ull pack2(float x, float y){
    ull r; asm("mov.b64 %0, {%1, %2};" : "=l"(r) : "f"(x), "f"(y)); return r;
}
__device__ __forceinline__ float2 unpack2(ull v){
    float2 r; asm("mov.b64 {%0, %1}, %2;" : "=f"(r.x), "=f"(r.y) : "l"(v)); return r;
}

// ---- kernel 0: pad x [B,T,15] -> [B,T,16], float4 both directions via smem ----
__global__ void __launch_bounds__(256) pad_x_kernel(const float* __restrict__ x){
    __shared__ float xsm[256*IDIM];
    const int tid = threadIdx.x;
    const float4* src4 = (const float4*)(x + (size_t)blockIdx.x * (256*IDIM));
    #pragma unroll
    for (int k=0;k<4;k++){
        int idx = tid + k*256;
        if (idx < 960) ((float4*)xsm)[idx] = src4[idx];
    }
    __syncthreads();
    float4* dst4 = (float4*)(g_xpad + (size_t)blockIdx.x * (256*16));
    #pragma unroll
    for (int k=0;k<4;k++){
        int idx = tid + k*256;
        int row = idx >> 2, q = idx & 3;
        const float* rp = xsm + row*IDIM + q*4;
        float f0 = rp[0], f1 = rp[1], f2 = rp[2];
        float f3 = (q == 3) ? 0.f : rp[3];
        dst4[idx] = make_float4(f0, f1, f2, f3);
    }
}

// ---- kernel 1: fused xproj + recurrence + decoder. warp == one batch ----
__global__ void __launch_bounds__(128,1) rnn_dec_kernel(
    const float* __restrict__ W_ih, const float* __restrict__ b_ih,
    const float* __restrict__ W_hh, const float* __restrict__ b_hh,
    const float* __restrict__ W_dec, const float* __restrict__ b_dec,
    float* __restrict__ out, float* __restrict__ h_out)
{
    __shared__ __align__(16) float xs[2][4][CHUNK*16];   // x chunks: 2 x 4 x 1KB = 8KB
    __shared__ __align__(16) ull  h_sh[4][2][32];        // per-warp double-buffered h

    const int wid = threadIdx.x >> 5;
    const int l   = threadIdx.x & 31;
    const int b   = blockIdx.x * 4 + wid;
    const int j0  = 2*l, j1 = j0 + 1;

    // W_hh rows j0,j1 in registers, k-paired as f32x2 (128 regs)
    ull w0[32], w1[32];
    {
        const ull* wp = (const ull*)W_hh;
        #pragma unroll
        for (int q=0;q<32;q++){ w0[q] = wp[j0*32+q]; w1[q] = wp[j1*32+q]; }
    }
    // W_ih rows j0,j1, i-paired (i=15 padded with 0)
    ull wi0[8], wi1[8];
    #pragma unroll
    for (int q=0;q<8;q++){
        float a0 = W_ih[j0*IDIM + 2*q];
        float a1 = (2*q+1 < IDIM) ? W_ih[j0*IDIM + 2*q + 1] : 0.f;
        wi0[q] = pack2(a0,a1);
        float c0 = W_ih[j1*IDIM + 2*q];
        float c1 = (2*q+1 < IDIM) ? W_ih[j1*IDIM + 2*q + 1] : 0.f;
        wi1[q] = pack2(c0,c1);
    }
    const ull bias0 = pack2(b_ih[j0]+b_hh[j0], 0.f);
    const ull bias1 = pack2(b_ih[j1]+b_hh[j1], 0.f);

    // decoder weights: lane l<22 handles output o=l>>1, K-half = l&1 (16 ull)
    const int o = l >> 1, half = l & 1;
    ull wd[16];
    float bdec = 0.f;
    if (l < 22){
        const ull* wdp = (const ull*)W_dec;
        #pragma unroll
        for (int q=0;q<16;q++) wd[q] = wdp[o*32 + half*16 + q];
        bdec = b_dec[o];
    } else {
        #pragma unroll
        for (int q=0;q<16;q++) wd[q] = 0ULL;
    }

    h_sh[wid][1][l] = 0ULL;   // h_{-1} = 0 (t=0 reads slot 1)

    const uint32_t xs_base = (uint32_t)__cvta_generic_to_shared(&xs[0][wid][0]);
    const float* xsrc = g_xpad + (size_t)b * (TT*16);

    auto prefetch = [&](int c){
        if (c < NCHUNK){
            const float* src = xsrc + (size_t)c * (CHUNK*16);
            uint32_t dst = xs_base + (uint32_t)(c & 1) * (uint32_t)sizeof(xs[0]);
            #pragma unroll
            for (int q=0;q<2;q++){
                int idx = q*32 + l;   // 64 x 16B
                asm volatile("cp.async.ca.shared.global [%0], [%1], 16;\n"
                    :: "r"(dst + (uint32_t)(idx*16)), "l"(src + idx*4) : "memory");
            }
        }
        asm volatile("cp.async.commit_group;\n" ::: "memory");
    };

    prefetch(0);
    float* outp = out + (size_t)b * (TT*ODIM);

    // software-pipelined xproj accumulators (for the CURRENT step)
    ull xa0 = bias0, xa1 = bias1;   // will be t=0's xproj after first compute
    bool xa_valid = false;

    for (int c=0; c<NCHUNK; c++){
        prefetch(c+1);
        asm volatile("cp.async.wait_group 1;\n" ::: "memory");
        __syncwarp();
        const float* xpb = &xs[c & 1][wid][0];

        // first chunk: compute xproj for t=0 before entering the steady loop
        if (!xa_valid){
            const ulonglong2* xv = (const ulonglong2*)(xpb);
            #pragma unroll
            for (int q=0;q<4;q++){
                ulonglong2 xq = xv[q];
                xa0 = ffma2(xq.x, wi0[2*q],   xa0);
                xa1 = ffma2(xq.x, wi1[2*q],   xa1);
                xa0 = ffma2(xq.y, wi0[2*q+1], xa0);
                xa1 = ffma2(xq.y, wi1[2*q+1], xa1);
            }
            xa_valid = true;
        }

        #pragma unroll 2
        for (int tt=0; tt<CHUNK; tt++){
            const int rs = (tt & 1) ^ 1;   // slot holding h_{t-1}
            const int ws =  tt & 1;        // slot for h_t
            const int t  = c*CHUNK + tt;

            // ---- recurrence + decoder share the same h LDS stream ----
            const ulonglong2* hp = (const ulonglong2*)&h_sh[wid][rs][0];
            ull aa0=0ULL, aa1=0ULL, ab0=0ULL, ab1=0ULL;
            ull d0=0ULL, d1=0ULL;
            #pragma unroll
            for (int q=0;q<16;q++){
                ulonglong2 hv = hp[q];
                aa0 = ffma2(hv.x, w0[2*q],   aa0);
                aa1 = ffma2(hv.x, w1[2*q],   aa1);
                ab0 = ffma2(hv.y, w0[2*q+1], ab0);
                ab1 = ffma2(hv.y, w1[2*q+1], ab1);
                // dec uses hv q-range [half*8, half*8+8) — no extra LDS
                if (q >= half*8 && q < half*8 + 8){
                    int qq = q - half*8;
                    d0 = ffma2(hv.x, wd[2*qq],   d0);
                    d1 = ffma2(hv.y, wd[2*qq+1], d1);
                }
            }

            // ---- xproj for NEXT step (independent of h; fills chain-wait slots) ----
            ull nxa0 = bias0, nxa1 = bias1;
            {
                const int ntt = tt + 1;
                const float* nxp = (ntt < CHUNK) ? (xpb + ntt*16)
                                                 : &xs[(c+1) & 1][wid][0];
                // guard: last chunk's last step has no next; reading stale smem is
                // harmless (result unused)
                const ulonglong2* xv = (const ulonglong2*)nxp;
                #pragma unroll
                for (int q=0;q<4;q++){
                    ulonglong2 xq = xv[q];
                    nxa0 = ffma2(xq.x, wi0[2*q],   nxa0);
                    nxa1 = ffma2(xq.x, wi1[2*q],   nxa1);
                    nxa0 = ffma2(xq.y, wi0[2*q+1], nxa0);
                    nxa1 = ffma2(xq.y, wi1[2*q+1], nxa1);
                }
            }

            // ---- decoder finalize (emits step t-1) ----
            float2 ds = unpack2(fadd2(d0,d1));
            float dp = ds.x + ds.y;
            float dq = __shfl_down_sync(0xffffffffu, dp, 1);

            // ---- recurrence finalize ----
            float2 s0 = unpack2(fadd2(fadd2(aa0, ab0), xa0));
            float2 s1 = unpack2(fadd2(fadd2(aa1, ab1), xa1));
            float h0v = fmaxf(s0.x + s0.y, 0.f);
            float h1v = fmaxf(s1.x + s1.y, 0.f);
            h_sh[wid][ws][l] = pack2(h0v, h1v);

            if (t > 0 && l < 22 && half == 0){
                outp[(size_t)(t-1)*ODIM + o] = fmaxf(dp + dq + bdec, 0.f);
            }

            xa0 = nxa0; xa1 = nxa1;
            __syncwarp();
        }
        // NOTE: xa for the first step of chunk c+1 was computed from the c+1
        // buffer BEFORE its cp.async completed -> recompute it after the wait.
        // Handled at top of next iteration:
        xa_valid = false;
        xa0 = bias0; xa1 = bias1;
    }

    // final decoder for t = T-1 (h_{1023} lives in slot 1) + final hidden state
    {
        const ulonglong2* hd = (const ulonglong2*)&h_sh[wid][1][half*16];
        ull d0=0ULL, d1=0ULL;
        #pragma unroll
        for (int q=0;q<8;q++){
            ulonglong2 hv = hd[q];
            d0 = ffma2(hv.x, wd[2*q],   d0);
            d1 = ffma2(hv.y, wd[2*q+1], d1);
        }
        float2 ds = unpack2(fadd2(d0,d1));
        float dp = ds.x + ds.y;
        float dq = __shfl_down_sync(0xffffffffu, dp, 1);
        if (l < 22 && half == 0){
            outp[(size_t)(TT-1)*ODIM + o] = fmaxf(dp + dq + bdec, 0.f);
        }
        ((ull*)h_out)[b*32 + l] = h_sh[wid][1][l];
    }
}

extern "C" void kernel_launch(void* const* d_in, const int* in_sizes, int n_in,
                              void* d_out, int out_size)
{
    const float* x     = (const float*)d_in[0];
    const float* W_ih  = (const float*)d_in[1];
    const float* b_ih  = (const float*)d_in[2];
    const float* W_hh  = (const float*)d_in[3];
    const float* b_hh  = (const float*)d_in[4];
    const float* W_dec = (const float*)d_in[5];
    const float* b_dec = (const float*)d_in[6];
    float* out = (float*)d_out;

    (void)in_sizes; (void)n_in; (void)out_size;

    pad_x_kernel<<<(BB*TT)/256, 256>>>(x);
    rnn_dec_kernel<<<BB/4, 128>>>(W_ih, b_ih, W_hh, b_hh, W_dec, b_dec,
                                  out, out + (size_t)BB*TT*ODIM);
}

// round 5
// speedup vs baseline: 1.0792x; 1.0792x over previous
#include <cuda_runtime.h>
#include <cstdint>

typedef unsigned long long ull;

#define BB 512
#define TT 1024
#define IDIM 15
#define HH 64
#define ODIM 11
#define CHUNK 8
#define NCHUNK (TT/CHUNK)

// scratch (static __device__ — no allocations in kernel_launch)
__device__ __align__(16) float g_xpad[(size_t)BB*TT*16];   // x padded 15 -> 16

// ---- f32x2 helpers ----
__device__ __forceinline__ ull ffma2(ull a, ull b, ull c){
    ull d; asm("fma.rn.f32x2 %0, %1, %2, %3;" : "=l"(d) : "l"(a), "l"(b), "l"(c)); return d;
}
__device__ __forceinline__ ull fadd2(ull a, ull b){
    ull d; asm("add.rn.f32x2 %0, %1, %2;" : "=l"(d) : "l"(a), "l"(b)); return d;
}
__device__ __forceinline__ ull pack2(float x, float y){
    ull r; asm("mov.b64 %0, {%1, %2};" : "=l"(r) : "f"(x), "f"(y)); return r;
}
__device__ __forceinline__ float2 unpack2(ull v){
    float2 r; asm("mov.b64 {%0, %1}, %2;" : "=f"(r.x), "=f"(r.y) : "l"(v)); return r;
}

// ---- kernel 0: pad x [B,T,15] -> [B,T,16], float4 both directions via smem ----
__global__ void __launch_bounds__(256) pad_x_kernel(const float* __restrict__ x){
    __shared__ float xsm[256*IDIM];
    const int tid = threadIdx.x;
    const float4* src4 = (const float4*)(x + (size_t)blockIdx.x * (256*IDIM));
    #pragma unroll
    for (int k=0;k<4;k++){
        int idx = tid + k*256;
        if (idx < 960) ((float4*)xsm)[idx] = src4[idx];
    }
    __syncthreads();
    float4* dst4 = (float4*)(g_xpad + (size_t)blockIdx.x * (256*16));
    #pragma unroll
    for (int k=0;k<4;k++){
        int idx = tid + k*256;
        int row = idx >> 2, q = idx & 3;
        const float* rp = xsm + row*IDIM + q*4;
        float f0 = rp[0], f1 = rp[1], f2 = rp[2];
        float f3 = (q == 3) ? 0.f : rp[3];
        dst4[idx] = make_float4(f0, f1, f2, f3);
    }
}

// ---- kernel 1: fused xproj + recurrence + chunk-batched decoder. warp == batch ----
__global__ void __launch_bounds__(128,1) rnn_dec_kernel(
    const float* __restrict__ W_ih, const float* __restrict__ b_ih,
    const float* __restrict__ W_hh, const float* __restrict__ b_hh,
    const float* __restrict__ W_dec, const float* __restrict__ b_dec,
    float* __restrict__ out, float* __restrict__ h_out)
{
    __shared__ __align__(16) float xs[2][4][CHUNK*16];    // x chunks: 2*4*512B = 4KB
    __shared__ __align__(16) ull  ring[4][CHUNK+1][32];   // per-warp h ring: 9KB

    const int wid = threadIdx.x >> 5;
    const int l   = threadIdx.x & 31;
    const int b   = blockIdx.x * 4 + wid;
    const int j0  = 2*l, j1 = j0 + 1;

    // W_hh rows j0,j1 in registers, k-paired as f32x2 (128 regs)
    ull w0[32], w1[32];
    {
        const ull* wp = (const ull*)W_hh;
        #pragma unroll
        for (int q=0;q<32;q++){ w0[q] = wp[j0*32+q]; w1[q] = wp[j1*32+q]; }
    }
    // W_ih rows j0,j1, i-paired (i=15 padded with 0)
    ull wi0[8], wi1[8];
    #pragma unroll
    for (int q=0;q<8;q++){
        float a0 = W_ih[j0*IDIM + 2*q];
        float a1 = (2*q+1 < IDIM) ? W_ih[j0*IDIM + 2*q + 1] : 0.f;
        wi0[q] = pack2(a0,a1);
        float c0 = W_ih[j1*IDIM + 2*q];
        float c1 = (2*q+1 < IDIM) ? W_ih[j1*IDIM + 2*q + 1] : 0.f;
        wi1[q] = pack2(c0,c1);
    }
    const ull bias0 = pack2(b_ih[j0]+b_hh[j0], 0.f);
    const ull bias1 = pack2(b_ih[j1]+b_hh[j1], 0.f);

    // decoder weights: lane l<22 handles output o=l>>1, K-half = l&1 (16 ull)
    const int o = l >> 1, half = l & 1;
    const bool dec_store = (l < 22) && (half == 0);
    ull wd[16];
    float bdec = 0.f;
    if (l < 22){
        const ull* wdp = (const ull*)W_dec;
        #pragma unroll
        for (int q=0;q<16;q++) wd[q] = wdp[o*32 + half*16 + q];
        bdec = b_dec[o];
    } else {
        #pragma unroll
        for (int q=0;q<16;q++) wd[q] = 0ULL;
    }

    ring[wid][0][l] = 0ULL;   // h_{-1} = 0

    const uint32_t xs_base = (uint32_t)__cvta_generic_to_shared(&xs[0][wid][0]);
    const float* xsrc = g_xpad + (size_t)b * (TT*16);

    // chunk = 8 steps x 16 floats = 512B per warp = 32 x 16B -> one cp.async/lane
    auto prefetch = [&](int c){
        if (c < NCHUNK){
            const float* src = xsrc + (size_t)c * (CHUNK*16);
            uint32_t dst = xs_base + (uint32_t)(c & 1) * (uint32_t)sizeof(xs[0]);
            asm volatile("cp.async.ca.shared.global [%0], [%1], 16;\n"
                :: "r"(dst + (uint32_t)(l*16)), "l"(src + l*4) : "memory");
        }
        asm volatile("cp.async.commit_group;\n" ::: "memory");
    };

    prefetch(0);
    float* outp = out + (size_t)b * (TT*ODIM);
    ull hlast = 0ULL;

    for (int c=0; c<NCHUNK; c++){
        prefetch(c+1);
        asm volatile("cp.async.wait_group 1;\n" ::: "memory");
        __syncwarp();
        const float* xpb = &xs[c & 1][wid][0];

        // ---- 8 sequential recurrence steps (ring indices compile-time) ----
        #pragma unroll
        for (int tt=0; tt<CHUNK; tt++){
            // xproj: 16 ffma2, independent of h (fills stall slots)
            const ulonglong2* xv = (const ulonglong2*)(xpb + tt*16);
            ull xa0 = bias0, xa1 = bias1;
            #pragma unroll
            for (int q=0;q<4;q++){
                ulonglong2 xq = xv[q];
                xa0 = ffma2(xq.x, wi0[2*q],   xa0);
                xa1 = ffma2(xq.x, wi1[2*q],   xa1);
                xa0 = ffma2(xq.y, wi0[2*q+1], xa0);
                xa1 = ffma2(xq.y, wi1[2*q+1], xa1);
            }
            // recurrence: 64 ffma2 over h_{t-1} broadcast from ring[tt]
            const ulonglong2* hp = (const ulonglong2*)&ring[wid][tt][0];
            ull aa0=0ULL, aa1=0ULL, ab0=0ULL, ab1=0ULL;
            #pragma unroll
            for (int q=0;q<16;q++){
                ulonglong2 hv = hp[q];
                aa0 = ffma2(hv.x, w0[2*q],   aa0);
                aa1 = ffma2(hv.x, w1[2*q],   aa1);
                ab0 = ffma2(hv.y, w0[2*q+1], ab0);
                ab1 = ffma2(hv.y, w1[2*q+1], ab1);
            }
            float2 s0 = unpack2(fadd2(fadd2(aa0, ab0), xa0));
            float2 s1 = unpack2(fadd2(fadd2(aa1, ab1), xa1));
            float h0v = fmaxf(s0.x + s0.y, 0.f);
            float h1v = fmaxf(s1.x + s1.y, 0.f);
            hlast = pack2(h0v, h1v);
            ring[wid][tt+1][l] = hlast;
            __syncwarp();
        }

        // ---- chunk-batched decoder: 8 independent dots, perfect ILP ----
        #pragma unroll
        for (int s=0; s<CHUNK; s++){
            const ulonglong2* hd = (const ulonglong2*)&ring[wid][s+1][half*16];
            ull d0=0ULL, d1=0ULL;
            #pragma unroll
            for (int q=0;q<8;q++){
                ulonglong2 hv = hd[q];
                d0 = ffma2(hv.x, wd[2*q],   d0);
                d1 = ffma2(hv.y, wd[2*q+1], d1);
            }
            float2 ds = unpack2(fadd2(d0,d1));
            float dp = ds.x + ds.y;
            float dq = __shfl_down_sync(0xffffffffu, dp, 1);
            if (dec_store){
                outp[(size_t)(c*CHUNK + s)*ODIM + o] = fmaxf(dp + dq + bdec, 0.f);
            }
        }

        // carry h_{chunk_end} into ring[0] for the next chunk
        ring[wid][0][l] = hlast;
        __syncwarp();
    }

    // final hidden state -> tail of d_out ( [1,B,H] )
    ((ull*)h_out)[b*32 + l] = hlast;
}

extern "C" void kernel_launch(void* const* d_in, const int* in_sizes, int n_in,
                              void* d_out, int out_size)
{
    const float* x     = (const float*)d_in[0];
    const float* W_ih  = (const float*)d_in[1];
    const float* b_ih  = (const float*)d_in[2];
    const float* W_hh  = (const float*)d_in[3];
    const float* b_hh  = (const float*)d_in[4];
    const float* W_dec = (const float*)d_in[5];
    const float* b_dec = (const float*)d_in[6];
    float* out = (float*)d_out;

    (void)in_sizes; (void)n_in; (void)out_size;

    pad_x_kernel<<<(BB*TT)/256, 256>>>(x);
    rnn_dec_kernel<<<BB/4, 128>>>(W_ih, b_ih, W_hh, b_hh, W_dec, b_dec,
                                  out, out + (size_t)BB*TT*ODIM);
}